// round 5
// baseline (speedup 1.0000x reference)
#include <cuda_runtime.h>

// Cosine similarity per row: a,b [16,4096,256] f32 -> out [16,4096] f32.
// out[r] = dot(a_r,b_r) * rsqrt(max(|a_r|^2,EPS)) * rsqrt(max(|b_r|^2,EPS))
//
// Persistent grid-stride warps, one row per warp-iteration.
// Software-pipelined: next row's 8 LDG.128 are issued BEFORE the current
// row's FMA tree + 15-SHFL butterfly, so DRAM requests keep flowing while
// the warp is in its dependent reduction chain.

#define EPSV 1e-12f

__global__ __launch_bounds__(256, 4)
void cosine_rows_persistent(const float4* __restrict__ a4,
                            const float4* __restrict__ b4,
                            float* __restrict__ out,
                            int n_rows)
{
    const int lane   = threadIdx.x & 31;
    const int gwarp  = (blockIdx.x * blockDim.x + threadIdx.x) >> 5;
    const int nwarps = (gridDim.x * blockDim.x) >> 5;

    int row = gwarp;
    if (row >= n_rows) return;

    // Prologue: load current row (4 x LDG.128 per lane across a and b).
    long base = (long)row * 64 + lane;
    float4 a0 = __ldg(a4 + base);
    float4 a1 = __ldg(a4 + base + 32);
    float4 b0 = __ldg(b4 + base);
    float4 b1 = __ldg(b4 + base + 32);

    for (;;) {
        const int  nrow = row + nwarps;
        const bool more = nrow < n_rows;

        // Prefetch next row before touching current data (keeps MLP high
        // during the reduction below).
        float4 na0, na1, nb0, nb1;
        if (more) {
            long nbase = (long)nrow * 64 + lane;
            na0 = __ldg(a4 + nbase);
            na1 = __ldg(a4 + nbase + 32);
            nb0 = __ldg(b4 + nbase);
            nb1 = __ldg(b4 + nbase + 32);
        }

        // Per-lane partial sums over 8 floats.
        float dot = a0.x * b0.x + a0.y * b0.y + a0.z * b0.z + a0.w * b0.w
                  + a1.x * b1.x + a1.y * b1.y + a1.z * b1.z + a1.w * b1.w;
        float sa  = a0.x * a0.x + a0.y * a0.y + a0.z * a0.z + a0.w * a0.w
                  + a1.x * a1.x + a1.y * a1.y + a1.z * a1.z + a1.w * a1.w;
        float sb  = b0.x * b0.x + b0.y * b0.y + b0.z * b0.z + b0.w * b0.w
                  + b1.x * b1.x + b1.y * b1.y + b1.z * b1.z + b1.w * b1.w;

        // Warp butterfly: 5 stages, 3 independent shuffles per stage.
        #pragma unroll
        for (int off = 16; off > 0; off >>= 1) {
            dot += __shfl_xor_sync(0xFFFFFFFFu, dot, off);
            sa  += __shfl_xor_sync(0xFFFFFFFFu, sa,  off);
            sb  += __shfl_xor_sync(0xFFFFFFFFu, sb,  off);
        }

        if (lane == 0) {
            float inv = rsqrtf(fmaxf(sa, EPSV)) * rsqrtf(fmaxf(sb, EPSV));
            out[row] = dot * inv;
        }

        if (!more) break;
        row = nrow;
        a0 = na0; a1 = na1; b0 = nb0; b1 = nb1;
    }
}

extern "C" void kernel_launch(void* const* d_in, const int* in_sizes, int n_in,
                              void* d_out, int out_size)
{
    const float4* a = (const float4*)d_in[0];
    const float4* b = (const float4*)d_in[1];
    float* out = (float*)d_out;

    const int n_rows = out_size;            // 16*4096 = 65536 rows

    // Persistent single wave: 152 SMs x 4 CTAs of 256 threads (4864 warps),
    // ~13.5 rows per warp via grid-stride.
    const int blocks = 152 * 4;

    cosine_rows_persistent<<<blocks, 256>>>(a, b, out, n_rows);
}

// round 6
// speedup vs baseline: 1.0013x; 1.0013x over previous
#include <cuda_runtime.h>

// Cosine similarity per row: a,b [16,4096,256] f32 -> out [16,4096] f32.
// out[r] = dot(a_r,b_r) * rsqrt(max(|a_r|^2,EPS)) * rsqrt(max(|b_r|^2,EPS))
//
// Persistent grid-stride warps, one row per warp-iteration.
// Software-pipelined: next row's 8 LDG.128 are issued BEFORE the current
// row's FMA tree + 15-SHFL butterfly, so DRAM requests keep flowing while
// the warp is in its dependent reduction chain.

#define EPSV 1e-12f

__global__ __launch_bounds__(256, 4)
void cosine_rows_persistent(const float4* __restrict__ a4,
                            const float4* __restrict__ b4,
                            float* __restrict__ out,
                            int n_rows)
{
    const int lane   = threadIdx.x & 31;
    const int gwarp  = (blockIdx.x * blockDim.x + threadIdx.x) >> 5;
    const int nwarps = (gridDim.x * blockDim.x) >> 5;

    int row = gwarp;
    if (row >= n_rows) return;

    // Prologue: load current row (4 x LDG.128 per lane across a and b).
    long base = (long)row * 64 + lane;
    float4 a0 = __ldg(a4 + base);
    float4 a1 = __ldg(a4 + base + 32);
    float4 b0 = __ldg(b4 + base);
    float4 b1 = __ldg(b4 + base + 32);

    for (;;) {
        const int  nrow = row + nwarps;
        const bool more = nrow < n_rows;

        // Prefetch next row before touching current data (keeps MLP high
        // during the reduction below).
        float4 na0, na1, nb0, nb1;
        if (more) {
            long nbase = (long)nrow * 64 + lane;
            na0 = __ldg(a4 + nbase);
            na1 = __ldg(a4 + nbase + 32);
            nb0 = __ldg(b4 + nbase);
            nb1 = __ldg(b4 + nbase + 32);
        }

        // Per-lane partial sums over 8 floats.
        float dot = a0.x * b0.x + a0.y * b0.y + a0.z * b0.z + a0.w * b0.w
                  + a1.x * b1.x + a1.y * b1.y + a1.z * b1.z + a1.w * b1.w;
        float sa  = a0.x * a0.x + a0.y * a0.y + a0.z * a0.z + a0.w * a0.w
                  + a1.x * a1.x + a1.y * a1.y + a1.z * a1.z + a1.w * a1.w;
        float sb  = b0.x * b0.x + b0.y * b0.y + b0.z * b0.z + b0.w * b0.w
                  + b1.x * b1.x + b1.y * b1.y + b1.z * b1.z + b1.w * b1.w;

        // Warp butterfly: 5 stages, 3 independent shuffles per stage.
        #pragma unroll
        for (int off = 16; off > 0; off >>= 1) {
            dot += __shfl_xor_sync(0xFFFFFFFFu, dot, off);
            sa  += __shfl_xor_sync(0xFFFFFFFFu, sa,  off);
            sb  += __shfl_xor_sync(0xFFFFFFFFu, sb,  off);
        }

        if (lane == 0) {
            float inv = rsqrtf(fmaxf(sa, EPSV)) * rsqrtf(fmaxf(sb, EPSV));
            out[row] = dot * inv;
        }

        if (!more) break;
        row = nrow;
        a0 = na0; a1 = na1; b0 = nb0; b1 = nb1;
    }
}

extern "C" void kernel_launch(void* const* d_in, const int* in_sizes, int n_in,
                              void* d_out, int out_size)
{
    const float4* a = (const float4*)d_in[0];
    const float4* b = (const float4*)d_in[1];
    float* out = (float*)d_out;

    const int n_rows = out_size;            // 16*4096 = 65536 rows

    // Persistent single wave: 152 SMs x 4 CTAs of 256 threads (4864 warps),
    // ~13.5 rows per warp via grid-stride.
    const int blocks = 152 * 4;

    cosine_rows_persistent<<<blocks, 256>>>(a, b, out, n_rows);
}